// round 15
// baseline (speedup 1.0000x reference)
#include <cuda_runtime.h>
#include <cstdint>

// Problem constants
constexpr int Bn   = 8;
constexpr int Cn   = 512;
constexpr int Tn   = 1024;
constexpr int NG   = 32;
constexpr int CPG  = Cn / NG;
constexpr int NH   = 8;
constexpr int CH   = 64;
constexpr float EPSV = 1e-5f;
constexpr float LOG2E = 1.4426950408889634f;
constexpr float QSC = 0.125f * LOG2E;   // folded into Q at QKV-GEMM epilogue

// Scratch (device globals: allocation-free rule)
__device__ uint16_t g_qkvh[Bn * 1536 * Tn];   // 24 MB bf16
__device__ float    g_a   [Bn * Cn   * Tn];   // 16 MB fp32
__device__ float2   g_gab [Bn * Cn];          // per-channel (ga, be)

// ---------------------------------------------------------------------------
// helpers
// ---------------------------------------------------------------------------
__device__ __forceinline__ uint32_t bfpack(float lo, float hi) {
    uint32_t r;
    asm("cvt.rn.bf16x2.f32 %0, %1, %2;" : "=r"(r) : "f"(hi), "f"(lo));
    return r;
}
__device__ __forceinline__ float ex2(float x) {
    float y;
    asm("ex2.approx.ftz.f32 %0, %1;" : "=f"(y) : "f"(x));
    return y;
}

__device__ __forceinline__ void mma_bf16(float* c,
    uint32_t a0, uint32_t a1, uint32_t a2, uint32_t a3,
    uint32_t b0, uint32_t b1)
{
    asm volatile(
        "mma.sync.aligned.m16n8k16.row.col.f32.bf16.bf16.f32 "
        "{%0,%1,%2,%3}, {%4,%5,%6,%7}, {%8,%9}, {%0,%1,%2,%3};\n"
        : "+f"(c[0]), "+f"(c[1]), "+f"(c[2]), "+f"(c[3])
        : "r"(a0), "r"(a1), "r"(a2), "r"(a3), "r"(b0), "r"(b1));
}

__device__ __forceinline__ void ldsm4(uint32_t& r0, uint32_t& r1,
                                      uint32_t& r2, uint32_t& r3, uint32_t a)
{
    asm volatile("ldmatrix.sync.aligned.m8n8.x4.shared.b16 {%0,%1,%2,%3}, [%4];"
        : "=r"(r0), "=r"(r1), "=r"(r2), "=r"(r3) : "r"(a));
}
__device__ __forceinline__ void ldsm4t(uint32_t& r0, uint32_t& r1,
                                       uint32_t& r2, uint32_t& r3, uint32_t a)
{
    asm volatile("ldmatrix.sync.aligned.m8n8.x4.trans.shared.b16 {%0,%1,%2,%3}, [%4];"
        : "=r"(r0), "=r"(r1), "=r"(r2), "=r"(r3) : "r"(a));
}
__device__ __forceinline__ void cpasync16(uint32_t dst, const void* src) {
    asm volatile("cp.async.cg.shared.global [%0], [%1], 16;"
                 :: "r"(dst), "l"(src) : "memory");
}
#define CP_COMMIT() asm volatile("cp.async.commit_group;" ::: "memory")
#define CP_WAIT0()  asm volatile("cp.async.wait_group 0;" ::: "memory")
#define CP_WAIT1()  asm volatile("cp.async.wait_group 1;" ::: "memory")

// ---------------------------------------------------------------------------
// GroupNorm statistics only: per-channel affine (ga, be) table.
// ga[c] = gamma[c]*rinv(b,g);  be[c] = beta[c] - mean(b,g)*ga[c].
// ---------------------------------------------------------------------------
__global__ __launch_bounds__(256) void gn_stats_kernel(
    const float* __restrict__ x, const float* __restrict__ gamma,
    const float* __restrict__ beta, float2* __restrict__ gab)
{
    int bg = blockIdx.x;
    int b = bg >> 5, g = bg & 31;
    const int CNT4 = CPG * Tn / 4;
    size_t base = ((size_t)b * Cn + g * CPG) * Tn;
    const float4* x4 = (const float4*)(x + base);

    float s = 0.f, s2 = 0.f;
    for (int i = threadIdx.x; i < CNT4; i += 256) {
        float4 v = x4[i];
        s  += v.x + v.y + v.z + v.w;
        s2 += v.x * v.x + v.y * v.y + v.z * v.z + v.w * v.w;
    }
    #pragma unroll
    for (int o = 16; o > 0; o >>= 1) {
        s  += __shfl_down_sync(0xffffffffu, s,  o);
        s2 += __shfl_down_sync(0xffffffffu, s2, o);
    }
    __shared__ float ws[8], ws2[8], sMean, sRinv;
    int wid = threadIdx.x >> 5, lane = threadIdx.x & 31;
    if (lane == 0) { ws[wid] = s; ws2[wid] = s2; }
    __syncthreads();
    if (threadIdx.x == 0) {
        float ts = 0.f, ts2 = 0.f;
        #pragma unroll
        for (int i = 0; i < 8; i++) { ts += ws[i]; ts2 += ws2[i]; }
        float mean = ts / (CPG * Tn);
        float var  = ts2 / (CPG * Tn) - mean * mean;
        sMean = mean;
        sRinv = rsqrtf(var + EPSV);
    }
    __syncthreads();
    if (threadIdx.x < CPG) {
        int c = g * CPG + threadIdx.x;
        float ga = gamma[c] * sRinv;
        gab[b * Cn + c] = make_float2(ga, beta[c] - sMean * ga);
    }
}

// ---------------------------------------------------------------------------
// bf16 tensor-core SGEMM, double-buffered pipeline.
// gab != null : X rows are normalized on the fly (fused GroupNorm).
// out_bf != null : write bf16 (Q rows scaled by QSC), no resid.
// out    != null : write fp32 (+bias, +resid).
// ---------------------------------------------------------------------------
constexpr int WS_W = 20;
constexpr int XS_W = 136;

__global__ __launch_bounds__(256, 2) void sgemm_bf16(
    const float* __restrict__ W, const float* __restrict__ X,
    const float* __restrict__ bias, const float* __restrict__ resid,
    const float2* __restrict__ gab,
    float* __restrict__ out, uint16_t* __restrict__ out_bf,
    int O, int C, int T)
{
    __shared__ uint32_t Ws[2][128 * WS_W];
    __shared__ uint32_t Xs[2][16 * XS_W];

    int b  = blockIdx.z;
    const float* Xb = X + (size_t)b * C * T;
    const float2* gb = gab ? gab + (size_t)b * Cn : nullptr;
    int m0 = blockIdx.y * 128, n0 = blockIdx.x * 128;

    int tid = threadIdx.x, warp = tid >> 5, lane = tid & 31;
    int gid = lane >> 2, tig = lane & 3;
    int wm = warp >> 1;
    int wn = warp & 1;

    int wm_e = tid >> 2,  wk_e = (tid & 3) * 8;
    int xk2_e = tid >> 5, xn_e = (tid & 31) * 4;

    float acc[2][8][4];
    #pragma unroll
    for (int mt = 0; mt < 2; mt++)
        #pragma unroll
        for (int nt = 0; nt < 8; nt++)
            #pragma unroll
            for (int q = 0; q < 4; q++) acc[mt][nt][q] = 0.f;

    float4 w00 = *(const float4*)&W[(size_t)(m0 + wm_e     ) * C + wk_e];
    float4 w01 = *(const float4*)&W[(size_t)(m0 + wm_e     ) * C + wk_e + 4];
    float4 w10 = *(const float4*)&W[(size_t)(m0 + wm_e + 64) * C + wk_e];
    float4 w11 = *(const float4*)&W[(size_t)(m0 + wm_e + 64) * C + wk_e + 4];
    float4 x00 = *(const float4*)&Xb[(size_t)(2 * xk2_e     ) * T + n0 + xn_e];
    float4 x01 = *(const float4*)&Xb[(size_t)(2 * xk2_e  + 1) * T + n0 + xn_e];
    float4 x10 = *(const float4*)&Xb[(size_t)(2 * xk2_e + 16) * T + n0 + xn_e];
    float4 x11 = *(const float4*)&Xb[(size_t)(2 * xk2_e + 17) * T + n0 + xn_e];

    int nk = C >> 5;
    for (int i = 0; i < nk; i++) {
        int p = i & 1;
        int ck = i << 5;   // k0 of the tile being committed
        if (gb) {
            float2 t0 = gb[ck + 2 * xk2_e];
            float2 t1 = gb[ck + 2 * xk2_e + 1];
            float2 t2 = gb[ck + 2 * xk2_e + 16];
            float2 t3 = gb[ck + 2 * xk2_e + 17];
            x00 = make_float4(x00.x*t0.x+t0.y, x00.y*t0.x+t0.y,
                              x00.z*t0.x+t0.y, x00.w*t0.x+t0.y);
            x01 = make_float4(x01.x*t1.x+t1.y, x01.y*t1.x+t1.y,
                              x01.z*t1.x+t1.y, x01.w*t1.x+t1.y);
            x10 = make_float4(x10.x*t2.x+t2.y, x10.y*t2.x+t2.y,
                              x10.z*t2.x+t2.y, x10.w*t2.x+t2.y);
            x11 = make_float4(x11.x*t3.x+t3.y, x11.y*t3.x+t3.y,
                              x11.z*t3.x+t3.y, x11.w*t3.x+t3.y);
        }
        *(uint4*)&Ws[p][wm_e * WS_W + (wk_e >> 1)] =
            make_uint4(bfpack(w00.x, w00.y), bfpack(w00.z, w00.w),
                       bfpack(w01.x, w01.y), bfpack(w01.z, w01.w));
        *(uint4*)&Ws[p][(wm_e + 64) * WS_W + (wk_e >> 1)] =
            make_uint4(bfpack(w10.x, w10.y), bfpack(w10.z, w10.w),
                       bfpack(w11.x, w11.y), bfpack(w11.z, w11.w));
        *(uint4*)&Xs[p][xk2_e * XS_W + xn_e] =
            make_uint4(bfpack(x00.x, x01.x), bfpack(x00.y, x01.y),
                       bfpack(x00.z, x01.z), bfpack(x00.w, x01.w));
        *(uint4*)&Xs[p][(xk2_e + 8) * XS_W + xn_e] =
            make_uint4(bfpack(x10.x, x11.x), bfpack(x10.y, x11.y),
                       bfpack(x10.z, x11.z), bfpack(x10.w, x11.w));
        __syncthreads();

        if (i + 1 < nk) {
            int k0 = (i + 1) << 5;
            w00 = *(const float4*)&W[(size_t)(m0 + wm_e     ) * C + k0 + wk_e];
            w01 = *(const float4*)&W[(size_t)(m0 + wm_e     ) * C + k0 + wk_e + 4];
            w10 = *(const float4*)&W[(size_t)(m0 + wm_e + 64) * C + k0 + wk_e];
            w11 = *(const float4*)&W[(size_t)(m0 + wm_e + 64) * C + k0 + wk_e + 4];
            x00 = *(const float4*)&Xb[(size_t)(k0 + 2 * xk2_e     ) * T + n0 + xn_e];
            x01 = *(const float4*)&Xb[(size_t)(k0 + 2 * xk2_e  + 1) * T + n0 + xn_e];
            x10 = *(const float4*)&Xb[(size_t)(k0 + 2 * xk2_e + 16) * T + n0 + xn_e];
            x11 = *(const float4*)&Xb[(size_t)(k0 + 2 * xk2_e + 17) * T + n0 + xn_e];
        }

        #pragma unroll
        for (int kh = 0; kh < 2; kh++) {
            int kho = kh * 8;
            uint32_t a[2][4];
            #pragma unroll
            for (int mt = 0; mt < 2; mt++) {
                int rbse = wm * 32 + mt * 16;
                a[mt][0] = Ws[p][(rbse + gid    ) * WS_W + kho + tig    ];
                a[mt][1] = Ws[p][(rbse + gid + 8) * WS_W + kho + tig    ];
                a[mt][2] = Ws[p][(rbse + gid    ) * WS_W + kho + tig + 4];
                a[mt][3] = Ws[p][(rbse + gid + 8) * WS_W + kho + tig + 4];
            }
            #pragma unroll
            for (int nt = 0; nt < 8; nt++) {
                int cb = wn * 64 + nt * 8;
                uint32_t b0 = Xs[p][(kho + tig    ) * XS_W + cb + gid];
                uint32_t b1 = Xs[p][(kho + tig + 4) * XS_W + cb + gid];
                #pragma unroll
                for (int mt = 0; mt < 2; mt++)
                    mma_bf16(acc[mt][nt], a[mt][0], a[mt][1], a[mt][2], a[mt][3], b0, b1);
            }
        }
    }

    // epilogue
    #pragma unroll
    for (int mt = 0; mt < 2; mt++) {
        #pragma unroll
        for (int rr = 0; rr < 2; rr++) {
            int m = m0 + wm * 32 + mt * 16 + gid + rr * 8;
            float bi = bias[m];
            if (out_bf) {
                uint16_t* ob = out_bf + (size_t)b * O * T;
                int m_rel = m % 192;
                float sc = (m_rel < 64) ? QSC : 1.0f;
                #pragma unroll
                for (int nt = 0; nt < 8; nt++) {
                    int n = n0 + wn * 64 + nt * 8 + 2 * tig;
                    float v0 = (acc[mt][nt][rr * 2 + 0] + bi) * sc;
                    float v1 = (acc[mt][nt][rr * 2 + 1] + bi) * sc;
                    *(uint32_t*)&ob[(size_t)m * T + n] = bfpack(v0, v1);
                }
            } else {
                float* outb = out + (size_t)b * O * T;
                const float* rb = resid + (size_t)b * O * T;
                #pragma unroll
                for (int nt = 0; nt < 8; nt++) {
                    int n = n0 + wn * 64 + nt * 8 + 2 * tig;
                    float v0 = acc[mt][nt][rr * 2 + 0] + bi + rb[(size_t)m * T + n];
                    float v1 = acc[mt][nt][rr * 2 + 1] + bi + rb[(size_t)m * T + n + 1];
                    *(float2*)&outb[(size_t)m * T + n] = make_float2(v0, v1);
                }
            }
        }
    }
}

// ---------------------------------------------------------------------------
// Flash attention (unchanged from R14): bf16 qkv, triple-buffered cp.async
// KV staging, Q fragments in registers, one barrier/iter, split-S overlap,
// register-resident P, max-free exp2 softmax.
// SMEM: 3 KV buffers x 128 rows x 272B = 104,448 B -> 2 CTAs/SM.
// ---------------------------------------------------------------------------
constexpr int ROWB     = 272;
constexpr int KV_BYTES = 128 * ROWB;                 // 34,816
constexpr int ATTN_SMEM_BYTES = 3 * KV_BYTES;        // 104,448

__global__ __launch_bounds__(256, 2) void attn_kernel(
    const uint16_t* __restrict__ qkvh, float* __restrict__ a_out)
{
    extern __shared__ uint8_t smraw[];
    uint32_t smem_b = (uint32_t)__cvta_generic_to_shared(smraw);

    int blk = blockIdx.x;
    int qt = blk & 7, hh = blk >> 3;
    int b = hh >> 3, h = hh & 7;
    const uint16_t* qg  = qkvh + (size_t)(b * 1536 + h * 192) * Tn;
    const uint16_t* kvg = qg + (size_t)64 * Tn;   // rows: 0-63 K, 64-127 V
    int i0 = qt * 128;

    int tid = threadIdx.x, warp = tid >> 5, lane = tid & 31;
    int gid = lane >> 2, tig = lane & 3;
    int rA = warp * 16 + gid;

    uint32_t q_off = (uint32_t)(((lane & 7) + ((lane >> 4) << 3)) * ROWB
                                + (warp * 16 + (((lane >> 3) & 1) << 3)) * 2);
    uint32_t k_off = (uint32_t)((lane & 15) * ROWB + ((lane >> 4) << 4));
    uint32_t v_off = (uint32_t)((64 + (lane & 7) + ((lane >> 4) << 3)) * ROWB
                                + (((lane >> 3) & 1) << 4));

    int sr = tid >> 1, shalf = tid & 1;
    int qr = tid >> 2, qq = tid & 3;

    // prologue: Q -> buf2, KV tile0 -> buf0, KV tile1 -> buf1, one group
    {
        const uint16_t* src = qg + (size_t)qr * Tn + i0 + qq * 32;
        uint32_t dst = smem_b + 2 * KV_BYTES + qr * ROWB + qq * 64;
        #pragma unroll
        for (int c = 0; c < 4; c++) cpasync16(dst + c * 16, src + c * 8);
    }
    #pragma unroll
    for (int t = 0; t < 2; t++) {
        const uint16_t* src = kvg + (size_t)sr * Tn + t * 128 + shalf * 64;
        uint32_t dst = smem_b + t * KV_BYTES + sr * ROWB + shalf * 128;
        #pragma unroll
        for (int c = 0; c < 8; c++) cpasync16(dst + c * 16, src + c * 8);
    }
    CP_COMMIT();
    CP_WAIT0();
    __syncthreads();

    uint32_t qa[4][4];
    #pragma unroll
    for (int kc = 0; kc < 4; kc++)
        ldsm4t(qa[kc][0], qa[kc][1], qa[kc][2], qa[kc][3],
               smem_b + 2 * KV_BYTES + q_off + kc * 16 * ROWB);

    float lrow0 = 0.f, lrow1 = 0.f;
    float oacc[8][4];
    #pragma unroll
    for (int nt = 0; nt < 8; nt++)
        #pragma unroll
        for (int q = 0; q < 4; q++) oacc[nt][q] = 0.f;

    int p = 0;
    for (int it = 0; it < 8; it++) {
        uint32_t kvb = smem_b + p * KV_BYTES;
        CP_WAIT1();
        __syncthreads();

        uint32_t pk[8][4];
        #pragma unroll
        for (int half = 0; half < 2; half++) {
            float sacc[8][4];
            #pragma unroll
            for (int j = 0; j < 8; j++)
                #pragma unroll
                for (int q = 0; q < 4; q++) sacc[j][q] = 0.f;

            #pragma unroll
            for (int kc = 0; kc < 4; kc++) {
                #pragma unroll
                for (int jp = 0; jp < 4; jp++) {
                    int nt = half * 4 + jp;
                    uint32_t b0, b1, b2, b3;
                    ldsm4t(b0, b1, b2, b3,
                           kvb + k_off + kc * 16 * ROWB + nt * 32);
                    mma_bf16(sacc[2 * jp    ], qa[kc][0], qa[kc][1],
                             qa[kc][2], qa[kc][3], b0, b1);
                    mma_bf16(sacc[2 * jp + 1], qa[kc][0], qa[kc][1],
                             qa[kc][2], qa[kc][3], b2, b3);
                }
            }
            #pragma unroll
            for (int j = 0; j < 8; j++) {
                sacc[j][0] = ex2(sacc[j][0]);
                sacc[j][1] = ex2(sacc[j][1]);
                sacc[j][2] = ex2(sacc[j][2]);
                sacc[j][3] = ex2(sacc[j][3]);
                lrow0 += sacc[j][0] + sacc[j][1];
                lrow1 += sacc[j][2] + sacc[j][3];
            }
            #pragma unroll
            for (int jp = 0; jp < 4; jp++) {
                int kbk = half * 4 + jp;
                pk[kbk][0] = bfpack(sacc[2 * jp    ][0], sacc[2 * jp    ][1]);
                pk[kbk][1] = bfpack(sacc[2 * jp    ][2], sacc[2 * jp    ][3]);
                pk[kbk][2] = bfpack(sacc[2 * jp + 1][0], sacc[2 * jp + 1][1]);
                pk[kbk][3] = bfpack(sacc[2 * jp + 1][2], sacc[2 * jp + 1][3]);
            }
        }

        #pragma unroll
        for (int kbk = 0; kbk < 8; kbk++) {
            #pragma unroll
            for (int ntp = 0; ntp < 4; ntp++) {
                uint32_t b0, b1, b2, b3;
                ldsm4(b0, b1, b2, b3, kvb + v_off + ntp * 16 * ROWB + kbk * 32);
                mma_bf16(oacc[2 * ntp    ], pk[kbk][0], pk[kbk][1],
                         pk[kbk][2], pk[kbk][3], b0, b1);
                mma_bf16(oacc[2 * ntp + 1], pk[kbk][0], pk[kbk][1],
                         pk[kbk][2], pk[kbk][3], b2, b3);
            }
        }

        if (it + 2 < 8) {
            int pf = p + 2; if (pf >= 3) pf -= 3;
            const uint16_t* src = kvg + (size_t)sr * Tn + (it + 2) * 128 + shalf * 64;
            uint32_t dst = smem_b + pf * KV_BYTES + sr * ROWB + shalf * 128;
            #pragma unroll
            for (int c = 0; c < 8; c++) cpasync16(dst + c * 16, src + c * 8);
        }
        CP_COMMIT();

        if (++p == 3) p = 0;
    }

    lrow0 += __shfl_xor_sync(0xffffffffu, lrow0, 1);
    lrow0 += __shfl_xor_sync(0xffffffffu, lrow0, 2);
    lrow1 += __shfl_xor_sync(0xffffffffu, lrow1, 1);
    lrow1 += __shfl_xor_sync(0xffffffffu, lrow1, 2);
    float inv0 = 1.f / lrow0, inv1 = 1.f / lrow1;
    size_t obase = ((size_t)b * Cn + h * CH) * Tn + i0;
    #pragma unroll
    for (int nt = 0; nt < 8; nt++) {
        int c = nt * 8 + 2 * tig;
        a_out[obase + (size_t)(c    ) * Tn + rA    ] = oacc[nt][0] * inv0;
        a_out[obase + (size_t)(c + 1) * Tn + rA    ] = oacc[nt][1] * inv0;
        a_out[obase + (size_t)(c    ) * Tn + rA + 8] = oacc[nt][2] * inv1;
        a_out[obase + (size_t)(c + 1) * Tn + rA + 8] = oacc[nt][3] * inv1;
    }
}

// ---------------------------------------------------------------------------
extern "C" void kernel_launch(void* const* d_in, const int* in_sizes, int n_in,
                              void* d_out, int out_size)
{
    const float* x      = (const float*)d_in[0];
    const float* gamma  = (const float*)d_in[1];
    const float* beta   = (const float*)d_in[2];
    const float* w_qkv  = (const float*)d_in[3];
    const float* b_qkv  = (const float*)d_in[4];
    const float* w_proj = (const float*)d_in[5];
    const float* b_proj = (const float*)d_in[6];
    float* out = (float*)d_out;

    float *a_ptr;
    uint16_t* qkvh_ptr;
    float2* gab_ptr;
    cudaGetSymbolAddress((void**)&qkvh_ptr, g_qkvh);
    cudaGetSymbolAddress((void**)&a_ptr,    g_a);
    cudaGetSymbolAddress((void**)&gab_ptr,  g_gab);

    cudaFuncSetAttribute(attn_kernel,
                         cudaFuncAttributeMaxDynamicSharedMemorySize,
                         ATTN_SMEM_BYTES);

    // 1. GroupNorm stats -> per-channel affine table
    gn_stats_kernel<<<Bn * NG, 256>>>(x, gamma, beta, gab_ptr);

    // 2. QKV GEMM with fused GroupNorm on X (bf16 out, Q pre-scaled)
    sgemm_bf16<<<dim3(Tn / 128, 1536 / 128, Bn), 256>>>(
        w_qkv, x, b_qkv, nullptr, gab_ptr, nullptr, qkvh_ptr, 1536, Cn, Tn);

    // 3. Attention
    attn_kernel<<<Bn * NH * (Tn / 128), 256, ATTN_SMEM_BYTES>>>(
        qkvh_ptr, a_ptr);

    // 4. Proj GEMM + bias + residual
    sgemm_bf16<<<dim3(Tn / 128, Cn / 128, Bn), 256>>>(
        w_proj, a_ptr, b_proj, x, nullptr, out, nullptr, Cn, Cn, Tn);
}

// round 16
// speedup vs baseline: 1.1193x; 1.1193x over previous
#include <cuda_runtime.h>
#include <cstdint>

// Problem constants
constexpr int Bn   = 8;
constexpr int Cn   = 512;
constexpr int Tn   = 1024;
constexpr int NG   = 32;
constexpr int CPG  = Cn / NG;
constexpr int NH   = 8;
constexpr int CH   = 64;
constexpr float EPSV = 1e-5f;
constexpr float LOG2E = 1.4426950408889634f;
constexpr float QSC = 0.125f * LOG2E;   // folded into Q at QKV-GEMM epilogue

// Scratch (device globals: allocation-free rule)
__device__ uint16_t g_qkvh[Bn * 1536 * Tn];   // 24 MB bf16
__device__ uint16_t g_xn  [Bn * Cn * Tn];     //  8 MB bf16 (normalized x)
__device__ uint16_t g_ah  [Bn * Cn * Tn];     //  8 MB bf16 (attention out)
__device__ uint16_t g_wqh [1536 * Cn];        // bf16 w_qkv
__device__ uint16_t g_wph [Cn * Cn];          // bf16 w_proj

// ---------------------------------------------------------------------------
// helpers
// ---------------------------------------------------------------------------
__device__ __forceinline__ uint32_t bfpack(float lo, float hi) {
    uint32_t r;
    asm("cvt.rn.bf16x2.f32 %0, %1, %2;" : "=r"(r) : "f"(hi), "f"(lo));
    return r;
}
__device__ __forceinline__ uint16_t bf1(float v) {
    return (uint16_t)(bfpack(v, 0.f) & 0xFFFFu);
}
__device__ __forceinline__ float ex2(float x) {
    float y;
    asm("ex2.approx.ftz.f32 %0, %1;" : "=f"(y) : "f"(x));
    return y;
}

__device__ __forceinline__ void mma_bf16(float* c,
    uint32_t a0, uint32_t a1, uint32_t a2, uint32_t a3,
    uint32_t b0, uint32_t b1)
{
    asm volatile(
        "mma.sync.aligned.m16n8k16.row.col.f32.bf16.bf16.f32 "
        "{%0,%1,%2,%3}, {%4,%5,%6,%7}, {%8,%9}, {%0,%1,%2,%3};\n"
        : "+f"(c[0]), "+f"(c[1]), "+f"(c[2]), "+f"(c[3])
        : "r"(a0), "r"(a1), "r"(a2), "r"(a3), "r"(b0), "r"(b1));
}

__device__ __forceinline__ void ldsm4(uint32_t& r0, uint32_t& r1,
                                      uint32_t& r2, uint32_t& r3, uint32_t a)
{
    asm volatile("ldmatrix.sync.aligned.m8n8.x4.shared.b16 {%0,%1,%2,%3}, [%4];"
        : "=r"(r0), "=r"(r1), "=r"(r2), "=r"(r3) : "r"(a));
}
__device__ __forceinline__ void ldsm4t(uint32_t& r0, uint32_t& r1,
                                       uint32_t& r2, uint32_t& r3, uint32_t a)
{
    asm volatile("ldmatrix.sync.aligned.m8n8.x4.trans.shared.b16 {%0,%1,%2,%3}, [%4];"
        : "=r"(r0), "=r"(r1), "=r"(r2), "=r"(r3) : "r"(a));
}
__device__ __forceinline__ void cpasync16(uint32_t dst, const void* src) {
    asm volatile("cp.async.cg.shared.global [%0], [%1], 16;"
                 :: "r"(dst), "l"(src) : "memory");
}
#define CP_COMMIT() asm volatile("cp.async.commit_group;" ::: "memory")
#define CP_WAIT0()  asm volatile("cp.async.wait_group 0;" ::: "memory")
#define CP_WAIT1()  asm volatile("cp.async.wait_group 1;" ::: "memory")

// ---------------------------------------------------------------------------
// Weight conversion fp32 -> bf16 (once per call; deterministic)
// ---------------------------------------------------------------------------
__global__ __launch_bounds__(256) void convw_kernel(
    const float* __restrict__ src, uint16_t* __restrict__ dst, int n4)
{
    int i = blockIdx.x * 256 + threadIdx.x;
    if (i < n4) {
        float4 v = ((const float4*)src)[i];
        ((uint2*)dst)[i] = make_uint2(bfpack(v.x, v.y), bfpack(v.z, v.w));
    }
}

// ---------------------------------------------------------------------------
// GroupNorm: stats + write normalized bf16 x
// ---------------------------------------------------------------------------
__global__ __launch_bounds__(256) void gn_kernel(
    const float* __restrict__ x, const float* __restrict__ gamma,
    const float* __restrict__ beta, uint16_t* __restrict__ xn)
{
    int bg = blockIdx.x;
    int b = bg >> 5, g = bg & 31;
    const int CNT4 = CPG * Tn / 4;
    size_t base = ((size_t)b * Cn + g * CPG) * Tn;
    const float4* x4 = (const float4*)(x + base);
    uint2* o2 = (uint2*)(xn + base);

    float s = 0.f, s2 = 0.f;
    for (int i = threadIdx.x; i < CNT4; i += 256) {
        float4 v = x4[i];
        s  += v.x + v.y + v.z + v.w;
        s2 += v.x * v.x + v.y * v.y + v.z * v.z + v.w * v.w;
    }
    #pragma unroll
    for (int o = 16; o > 0; o >>= 1) {
        s  += __shfl_down_sync(0xffffffffu, s,  o);
        s2 += __shfl_down_sync(0xffffffffu, s2, o);
    }
    __shared__ float ws[8], ws2[8], sMean, sRinv;
    int wid = threadIdx.x >> 5, lane = threadIdx.x & 31;
    if (lane == 0) { ws[wid] = s; ws2[wid] = s2; }
    __syncthreads();
    if (threadIdx.x == 0) {
        float ts = 0.f, ts2 = 0.f;
        #pragma unroll
        for (int i = 0; i < 8; i++) { ts += ws[i]; ts2 += ws2[i]; }
        float mean = ts / (CPG * Tn);
        float var  = ts2 / (CPG * Tn) - mean * mean;
        sMean = mean;
        sRinv = rsqrtf(var + EPSV);
    }
    __syncthreads();
    float mean = sMean, rinv = sRinv;
    for (int i = threadIdx.x; i < CNT4; i += 256) {
        int c = g * CPG + (i >> 8);
        float ga = gamma[c] * rinv, be = beta[c] - mean * gamma[c] * rinv;
        float4 v = x4[i];
        o2[i] = make_uint2(bfpack(v.x * ga + be, v.y * ga + be),
                           bfpack(v.z * ga + be, v.w * ga + be));
    }
}

// ---------------------------------------------------------------------------
// Pure-bf16 tensor-core GEMM with cp.async triple-buffered staging and
// ldmatrix fragments. out[b][m][n] = sum_k A[m][k] X[b][k][n] + bias.
// A: bf16 [O][C] row-major. X: bf16 [C][T] per batch, k-major rows.
// 128x128 tile, 8 warps (4m x 2n), k-step 32, one barrier per k-tile.
// SMEM rows: A 64B data + 16 pad = 80 (8-row LDSM phases cover all banks),
//            B 256B data + 16 pad = 272 (proven in attention's K path).
// ---------------------------------------------------------------------------
constexpr int GA_ROWB = 80;
constexpr int GB_ROWB = 272;
constexpr int GA_BYTES = 128 * GA_ROWB;           // 10,240
constexpr int GB_BYTES = 32 * GB_ROWB;            //  8,704
constexpr int GKT_BYTES = GA_BYTES + GB_BYTES;    // 18,944
constexpr int GEMM_SMEM = 3 * GKT_BYTES;          // 56,832

__global__ __launch_bounds__(256, 2) void gemm_bf16(
    const uint16_t* __restrict__ A, const uint16_t* __restrict__ X,
    const float* __restrict__ bias, const float* __restrict__ resid,
    float* __restrict__ out, uint16_t* __restrict__ out_bf,
    int O, int C, int T)
{
    extern __shared__ uint8_t smraw[];
    uint32_t smem_b = (uint32_t)__cvta_generic_to_shared(smraw);

    int b  = blockIdx.z;
    const uint16_t* Xb = X + (size_t)b * C * T;
    int m0 = blockIdx.y * 128, n0 = blockIdx.x * 128;

    int tid = threadIdx.x, warp = tid >> 5, lane = tid & 31;
    int gid = lane >> 2, tig = lane & 3;
    int wm = warp >> 1;     // m offset wm*32
    int wn = warp & 1;      // n offset wn*64

    // staging indices
    int ar = tid >> 1, ao = (tid & 1) * 32;            // A: row, 32B half
    int br = tid >> 3, bo = (tid & 7) * 32;            // B: row, 32B chunk

    // ldmatrix lane offsets (relative to buffer bases)
    uint32_t a_off = (uint32_t)((wm * 32 + (lane & 15)) * GA_ROWB
                                + ((lane >> 4) << 4));
    uint32_t b_off = (uint32_t)((lane & 15) * GB_ROWB + ((lane >> 4) << 4));

    float acc[2][8][4];
    #pragma unroll
    for (int mt = 0; mt < 2; mt++)
        #pragma unroll
        for (int nt = 0; nt < 8; nt++)
            #pragma unroll
            for (int q = 0; q < 4; q++) acc[mt][nt][q] = 0.f;

    int nk = C >> 5;

    // stage k-tile t into buffer pf
    auto stage = [&](int t, int pf) {
        uint32_t base = smem_b + pf * GKT_BYTES;
        int k0 = t << 5;
        const uint16_t* asrc = A + (size_t)(m0 + ar) * C + k0 + (tid & 1) * 16;
        uint32_t adst = base + ar * GA_ROWB + ao;
        cpasync16(adst,      asrc);
        cpasync16(adst + 16, asrc + 8);
        const uint16_t* bsrc = Xb + (size_t)(k0 + br) * T + n0 + (tid & 7) * 16;
        uint32_t bdst = base + GA_BYTES + br * GB_ROWB + bo;
        cpasync16(bdst,      bsrc);
        cpasync16(bdst + 16, bsrc + 8);
    };

    stage(0, 0); CP_COMMIT();
    stage(1, 1); CP_COMMIT();

    int p = 0;
    for (int i = 0; i < nk; i++) {
        uint32_t base = smem_b + p * GKT_BYTES;
        CP_WAIT1();
        __syncthreads();

        #pragma unroll
        for (int kh = 0; kh < 2; kh++) {
            uint32_t a[2][4];
            #pragma unroll
            for (int mt = 0; mt < 2; mt++)
                ldsm4(a[mt][0], a[mt][1], a[mt][2], a[mt][3],
                      base + a_off + mt * 16 * GA_ROWB + kh * 32);
            #pragma unroll
            for (int nc = 0; nc < 4; nc++) {
                uint32_t b0, b1, b2, b3;
                ldsm4t(b0, b1, b2, b3,
                       base + GA_BYTES + b_off + kh * 16 * GB_ROWB
                       + wn * 128 + nc * 32);
                #pragma unroll
                for (int mt = 0; mt < 2; mt++) {
                    mma_bf16(acc[mt][2 * nc    ], a[mt][0], a[mt][1],
                             a[mt][2], a[mt][3], b0, b1);
                    mma_bf16(acc[mt][2 * nc + 1], a[mt][0], a[mt][1],
                             a[mt][2], a[mt][3], b2, b3);
                }
            }
        }

        if (i + 2 < nk) {
            int pf = p + 2; if (pf >= 3) pf -= 3;
            stage(i + 2, pf);
        }
        CP_COMMIT();
        if (++p == 3) p = 0;
    }

    // epilogue
    #pragma unroll
    for (int mt = 0; mt < 2; mt++) {
        #pragma unroll
        for (int rr = 0; rr < 2; rr++) {
            int m = m0 + wm * 32 + mt * 16 + gid + rr * 8;
            float bi = bias[m];
            if (out_bf) {
                uint16_t* ob = out_bf + (size_t)b * O * T;
                int m_rel = m % 192;
                float sc = (m_rel < 64) ? QSC : 1.0f;
                #pragma unroll
                for (int nt = 0; nt < 8; nt++) {
                    int n = n0 + wn * 64 + nt * 8 + 2 * tig;
                    float v0 = (acc[mt][nt][rr * 2 + 0] + bi) * sc;
                    float v1 = (acc[mt][nt][rr * 2 + 1] + bi) * sc;
                    *(uint32_t*)&ob[(size_t)m * T + n] = bfpack(v0, v1);
                }
            } else {
                float* outb = out + (size_t)b * O * T;
                const float* rb = resid + (size_t)b * O * T;
                #pragma unroll
                for (int nt = 0; nt < 8; nt++) {
                    int n = n0 + wn * 64 + nt * 8 + 2 * tig;
                    float v0 = acc[mt][nt][rr * 2 + 0] + bi + rb[(size_t)m * T + n];
                    float v1 = acc[mt][nt][rr * 2 + 1] + bi + rb[(size_t)m * T + n + 1];
                    *(float2*)&outb[(size_t)m * T + n] = make_float2(v0, v1);
                }
            }
        }
    }
}

// ---------------------------------------------------------------------------
// Flash attention (R14 structure): bf16 qkv, triple-buffered cp.async KV
// staging, Q fragments in registers, one barrier/iter, split-S overlap,
// register-resident P, max-free exp2 softmax. Output now bf16 (same
// rounding the proj staging used to apply).
// ---------------------------------------------------------------------------
constexpr int ROWB     = 272;
constexpr int KV_BYTES = 128 * ROWB;                 // 34,816
constexpr int ATTN_SMEM_BYTES = 3 * KV_BYTES;        // 104,448

__global__ __launch_bounds__(256, 2) void attn_kernel(
    const uint16_t* __restrict__ qkvh, uint16_t* __restrict__ a_out)
{
    extern __shared__ uint8_t smraw[];
    uint32_t smem_b = (uint32_t)__cvta_generic_to_shared(smraw);

    int blk = blockIdx.x;
    int qt = blk & 7, hh = blk >> 3;
    int b = hh >> 3, h = hh & 7;
    const uint16_t* qg  = qkvh + (size_t)(b * 1536 + h * 192) * Tn;
    const uint16_t* kvg = qg + (size_t)64 * Tn;   // rows: 0-63 K, 64-127 V
    int i0 = qt * 128;

    int tid = threadIdx.x, warp = tid >> 5, lane = tid & 31;
    int gid = lane >> 2, tig = lane & 3;
    int rA = warp * 16 + gid;

    uint32_t q_off = (uint32_t)(((lane & 7) + ((lane >> 4) << 3)) * ROWB
                                + (warp * 16 + (((lane >> 3) & 1) << 3)) * 2);
    uint32_t k_off = (uint32_t)((lane & 15) * ROWB + ((lane >> 4) << 4));
    uint32_t v_off = (uint32_t)((64 + (lane & 7) + ((lane >> 4) << 3)) * ROWB
                                + (((lane >> 3) & 1) << 4));

    int sr = tid >> 1, shalf = tid & 1;
    int qr = tid >> 2, qq = tid & 3;

    // prologue: Q -> buf2, KV tile0 -> buf0, KV tile1 -> buf1, one group
    {
        const uint16_t* src = qg + (size_t)qr * Tn + i0 + qq * 32;
        uint32_t dst = smem_b + 2 * KV_BYTES + qr * ROWB + qq * 64;
        #pragma unroll
        for (int c = 0; c < 4; c++) cpasync16(dst + c * 16, src + c * 8);
    }
    #pragma unroll
    for (int t = 0; t < 2; t++) {
        const uint16_t* src = kvg + (size_t)sr * Tn + t * 128 + shalf * 64;
        uint32_t dst = smem_b + t * KV_BYTES + sr * ROWB + shalf * 128;
        #pragma unroll
        for (int c = 0; c < 8; c++) cpasync16(dst + c * 16, src + c * 8);
    }
    CP_COMMIT();
    CP_WAIT0();
    __syncthreads();

    uint32_t qa[4][4];
    #pragma unroll
    for (int kc = 0; kc < 4; kc++)
        ldsm4t(qa[kc][0], qa[kc][1], qa[kc][2], qa[kc][3],
               smem_b + 2 * KV_BYTES + q_off + kc * 16 * ROWB);

    float lrow0 = 0.f, lrow1 = 0.f;
    float oacc[8][4];
    #pragma unroll
    for (int nt = 0; nt < 8; nt++)
        #pragma unroll
        for (int q = 0; q < 4; q++) oacc[nt][q] = 0.f;

    int p = 0;
    for (int it = 0; it < 8; it++) {
        uint32_t kvb = smem_b + p * KV_BYTES;
        CP_WAIT1();
        __syncthreads();

        uint32_t pk[8][4];
        #pragma unroll
        for (int half = 0; half < 2; half++) {
            float sacc[8][4];
            #pragma unroll
            for (int j = 0; j < 8; j++)
                #pragma unroll
                for (int q = 0; q < 4; q++) sacc[j][q] = 0.f;

            #pragma unroll
            for (int kc = 0; kc < 4; kc++) {
                #pragma unroll
                for (int jp = 0; jp < 4; jp++) {
                    int nt = half * 4 + jp;
                    uint32_t b0, b1, b2, b3;
                    ldsm4t(b0, b1, b2, b3,
                           kvb + k_off + kc * 16 * ROWB + nt * 32);
                    mma_bf16(sacc[2 * jp    ], qa[kc][0], qa[kc][1],
                             qa[kc][2], qa[kc][3], b0, b1);
                    mma_bf16(sacc[2 * jp + 1], qa[kc][0], qa[kc][1],
                             qa[kc][2], qa[kc][3], b2, b3);
                }
            }
            #pragma unroll
            for (int j = 0; j < 8; j++) {
                sacc[j][0] = ex2(sacc[j][0]);
                sacc[j][1] = ex2(sacc[j][1]);
                sacc[j][2] = ex2(sacc[j][2]);
                sacc[j][3] = ex2(sacc[j][3]);
                lrow0 += sacc[j][0] + sacc[j][1];
                lrow1 += sacc[j][2] + sacc[j][3];
            }
            #pragma unroll
            for (int jp = 0; jp < 4; jp++) {
                int kbk = half * 4 + jp;
                pk[kbk][0] = bfpack(sacc[2 * jp    ][0], sacc[2 * jp    ][1]);
                pk[kbk][1] = bfpack(sacc[2 * jp    ][2], sacc[2 * jp    ][3]);
                pk[kbk][2] = bfpack(sacc[2 * jp + 1][0], sacc[2 * jp + 1][1]);
                pk[kbk][3] = bfpack(sacc[2 * jp + 1][2], sacc[2 * jp + 1][3]);
            }
        }

        #pragma unroll
        for (int kbk = 0; kbk < 8; kbk++) {
            #pragma unroll
            for (int ntp = 0; ntp < 4; ntp++) {
                uint32_t b0, b1, b2, b3;
                ldsm4(b0, b1, b2, b3, kvb + v_off + ntp * 16 * ROWB + kbk * 32);
                mma_bf16(oacc[2 * ntp    ], pk[kbk][0], pk[kbk][1],
                         pk[kbk][2], pk[kbk][3], b0, b1);
                mma_bf16(oacc[2 * ntp + 1], pk[kbk][0], pk[kbk][1],
                         pk[kbk][2], pk[kbk][3], b2, b3);
            }
        }

        if (it + 2 < 8) {
            int pf = p + 2; if (pf >= 3) pf -= 3;
            const uint16_t* src = kvg + (size_t)sr * Tn + (it + 2) * 128 + shalf * 64;
            uint32_t dst = smem_b + pf * KV_BYTES + sr * ROWB + shalf * 128;
            #pragma unroll
            for (int c = 0; c < 8; c++) cpasync16(dst + c * 16, src + c * 8);
        }
        CP_COMMIT();

        if (++p == 3) p = 0;
    }

    lrow0 += __shfl_xor_sync(0xffffffffu, lrow0, 1);
    lrow0 += __shfl_xor_sync(0xffffffffu, lrow0, 2);
    lrow1 += __shfl_xor_sync(0xffffffffu, lrow1, 1);
    lrow1 += __shfl_xor_sync(0xffffffffu, lrow1, 2);
    float inv0 = 1.f / lrow0, inv1 = 1.f / lrow1;
    size_t obase = ((size_t)b * Cn + h * CH) * Tn + i0;
    #pragma unroll
    for (int nt = 0; nt < 8; nt++) {
        int c = nt * 8 + 2 * tig;
        a_out[obase + (size_t)(c    ) * Tn + rA    ] = bf1(oacc[nt][0] * inv0);
        a_out[obase + (size_t)(c + 1) * Tn + rA    ] = bf1(oacc[nt][1] * inv0);
        a_out[obase + (size_t)(c    ) * Tn + rA + 8] = bf1(oacc[nt][2] * inv1);
        a_out[obase + (size_t)(c + 1) * Tn + rA + 8] = bf1(oacc[nt][3] * inv1);
    }
}

// ---------------------------------------------------------------------------
extern "C" void kernel_launch(void* const* d_in, const int* in_sizes, int n_in,
                              void* d_out, int out_size)
{
    const float* x      = (const float*)d_in[0];
    const float* gamma  = (const float*)d_in[1];
    const float* beta   = (const float*)d_in[2];
    const float* w_qkv  = (const float*)d_in[3];
    const float* b_qkv  = (const float*)d_in[4];
    const float* w_proj = (const float*)d_in[5];
    const float* b_proj = (const float*)d_in[6];
    float* out = (float*)d_out;

    uint16_t *qkvh_ptr, *xn_ptr, *ah_ptr, *wqh_ptr, *wph_ptr;
    cudaGetSymbolAddress((void**)&qkvh_ptr, g_qkvh);
    cudaGetSymbolAddress((void**)&xn_ptr,   g_xn);
    cudaGetSymbolAddress((void**)&ah_ptr,   g_ah);
    cudaGetSymbolAddress((void**)&wqh_ptr,  g_wqh);
    cudaGetSymbolAddress((void**)&wph_ptr,  g_wph);

    cudaFuncSetAttribute(attn_kernel,
                         cudaFuncAttributeMaxDynamicSharedMemorySize,
                         ATTN_SMEM_BYTES);
    cudaFuncSetAttribute(gemm_bf16,
                         cudaFuncAttributeMaxDynamicSharedMemorySize,
                         GEMM_SMEM);

    // 0. convert w_qkv -> bf16       (1536*512/4 = 196608 float4s)
    convw_kernel<<<768, 256>>>(w_qkv, wqh_ptr, 1536 * Cn / 4);
    // 1. convert w_proj -> bf16      (512*512/4 = 65536 float4s)
    convw_kernel<<<256, 256>>>(w_proj, wph_ptr, Cn * Cn / 4);
    // 2. GroupNorm -> normalized bf16 x
    gn_kernel<<<Bn * NG, 256>>>(x, gamma, beta, xn_ptr);
    // 3. QKV GEMM (pure bf16, cp.async)   <- profiler capture slot
    gemm_bf16<<<dim3(Tn / 128, 1536 / 128, Bn), 256, GEMM_SMEM>>>(
        wqh_ptr, xn_ptr, b_qkv, nullptr, nullptr, qkvh_ptr, 1536, Cn, Tn);
    // 4. Attention (bf16 out)
    attn_kernel<<<Bn * NH * (Tn / 128), 256, ATTN_SMEM_BYTES>>>(
        qkvh_ptr, ah_ptr);
    // 5. Proj GEMM + bias + residual (fp32 out)
    gemm_bf16<<<dim3(Tn / 128, Cn / 128, Bn), 256, GEMM_SMEM>>>(
        wph_ptr, ah_ptr, b_proj, x, out, nullptr, Cn, Cn, Tn);
}